// round 5
// baseline (speedup 1.0000x reference)
#include <cuda_runtime.h>
#include <cuda_fp16.h>
#include <mma.h>
#include <cstdint>

#define NN 512
#define DD 256
#define HH 256
#define EE 128
#define TJ 128
#define TI 16

// Arch-specific (sm_103a) pass detection: tcgen05 only exists there.
#if defined(__CUDA_ARCH__) && (defined(__CUDA_ARCH_FEAT_SM103_ALL) || defined(__CUDA_ARCH_FEAT_SM100_ALL) || defined(__CUDA_ARCH_SPECIFIC__))
#define HAS_TCGEN05 1
#else
#define HAS_TCGEN05 0
#endif

// ---------------- static device scratch ----------------
__device__ __align__(128) float  g_s[NN * DD];
__device__ __align__(128) __half g_qh[NN * HH];     // q fp16 [j][h]
__device__ __align__(128) __half g_kh[NN * HH];     // k fp16 [i][h]
__device__ __align__(128) __half g_wpB[HH * EE];    // w_p SW128 blocked-atom image
__device__ __align__(128) __half g_wpT[HH * EE];    // w_p transposed linear (wmma fallback)
__device__ __align__(128) float  g_aq[NN * EE];     // q @ w_d^T
__device__ __align__(128) float  g_bkp[NN * EE];    // o_b - k @ w_d^T

// ---------------- PTX helpers ----------------
__device__ __forceinline__ uint32_t smem_u32(const void* p) {
    uint32_t a;
    asm("{ .reg .u64 t; cvta.to.shared.u64 t, %1; cvt.u32.u64 %0, t; }" : "=r"(a) : "l"(p));
    return a;
}

#if HAS_TCGEN05
__device__ __forceinline__ uint32_t elect_one() {
    uint32_t p;
    asm volatile("{ .reg .pred p; elect.sync _|p, 0xFFFFFFFF; selp.b32 %0, 1, 0, p; }" : "=r"(p));
    return p;
}
#define TC_ALLOC(dst, n) \
    asm volatile("tcgen05.alloc.cta_group::1.sync.aligned.shared::cta.b32 [%0], %1;" \
                 :: "r"(dst), "r"(n) : "memory")
#define TC_RELINQ() \
    asm volatile("tcgen05.relinquish_alloc_permit.cta_group::1.sync.aligned;")
#define TC_DEALLOC(base, n) \
    asm volatile("tcgen05.dealloc.cta_group::1.sync.aligned.b32 %0, %1;" :: "r"(base), "r"(n))
#define TC_WAIT_ST() asm volatile("tcgen05.wait::st.sync.aligned;" ::: "memory")
#define TC_WAIT_LD() asm volatile("tcgen05.wait::ld.sync.aligned;" ::: "memory")
#define TC_FENCE_BEFORE() asm volatile("tcgen05.fence::before_thread_sync;" ::: "memory")
#define TC_FENCE_AFTER()  asm volatile("tcgen05.fence::after_thread_sync;" ::: "memory")
#define TC_COMMIT(mbar) \
    asm volatile("tcgen05.commit.cta_group::1.mbarrier::arrive::one.shared::cluster.b64 [%0];" \
                 :: "r"(mbar) : "memory")
#define MBAR_INIT(a, c) \
    asm volatile("mbarrier.init.shared.b64 [%0], %1;" :: "r"(a), "r"(c) : "memory")
#define MBAR_INVAL(a) \
    asm volatile("mbarrier.inval.shared.b64 [%0];" :: "r"(a) : "memory")

#define MBAR_WAIT(mbar, par) do {                                              \
    uint32_t _m = (mbar), _p = (par), _d;                                      \
    asm volatile("{ .reg .pred p; mbarrier.try_wait.parity.acquire.cta.shared::cta.b64 p, [%1], %2; selp.b32 %0, 1, 0, p; }" \
        : "=r"(_d) : "r"(_m), "r"(_p) : "memory");                             \
    if (!_d) {                                                                 \
        asm volatile("{ .reg .pred P1; WL_%=: mbarrier.try_wait.parity.acquire.cta.shared::cta.b64 P1, [%0], %1, 0x989680; @P1 bra.uni WD_%=; bra.uni WL_%=; WD_%=: }" \
            :: "r"(_m), "r"(_p) : "memory");                                   \
    }                                                                          \
} while (0)

#define TC_ST_X32(addr, r)                                                     \
    asm volatile("tcgen05.st.sync.aligned.32x32b.x32.b32 [%0], "               \
        "{%1,%2,%3,%4,%5,%6,%7,%8,%9,%10,%11,%12,%13,%14,%15,%16,"            \
        "%17,%18,%19,%20,%21,%22,%23,%24,%25,%26,%27,%28,%29,%30,%31,%32};"    \
        :: "r"(addr),                                                          \
        "r"((r)[0]),"r"((r)[1]),"r"((r)[2]),"r"((r)[3]),"r"((r)[4]),"r"((r)[5]),"r"((r)[6]),"r"((r)[7]), \
        "r"((r)[8]),"r"((r)[9]),"r"((r)[10]),"r"((r)[11]),"r"((r)[12]),"r"((r)[13]),"r"((r)[14]),"r"((r)[15]), \
        "r"((r)[16]),"r"((r)[17]),"r"((r)[18]),"r"((r)[19]),"r"((r)[20]),"r"((r)[21]),"r"((r)[22]),"r"((r)[23]), \
        "r"((r)[24]),"r"((r)[25]),"r"((r)[26]),"r"((r)[27]),"r"((r)[28]),"r"((r)[29]),"r"((r)[30]),"r"((r)[31]) \
        : "memory")

#define TC_LD_X32(r, addr)                                                     \
    asm volatile("tcgen05.ld.sync.aligned.32x32b.x32.b32 "                     \
        "{%0,%1,%2,%3,%4,%5,%6,%7,%8,%9,%10,%11,%12,%13,%14,%15,"             \
        "%16,%17,%18,%19,%20,%21,%22,%23,%24,%25,%26,%27,%28,%29,%30,%31}, [%32];" \
        : "=r"((r)[0]),"=r"((r)[1]),"=r"((r)[2]),"=r"((r)[3]),"=r"((r)[4]),"=r"((r)[5]),"=r"((r)[6]),"=r"((r)[7]), \
          "=r"((r)[8]),"=r"((r)[9]),"=r"((r)[10]),"=r"((r)[11]),"=r"((r)[12]),"=r"((r)[13]),"=r"((r)[14]),"=r"((r)[15]), \
          "=r"((r)[16]),"=r"((r)[17]),"=r"((r)[18]),"=r"((r)[19]),"=r"((r)[20]),"=r"((r)[21]),"=r"((r)[22]),"=r"((r)[23]), \
          "=r"((r)[24]),"=r"((r)[25]),"=r"((r)[26]),"=r"((r)[27]),"=r"((r)[28]),"=r"((r)[29]),"=r"((r)[30]),"=r"((r)[31]) \
        : "r"(addr))

#define TC_MMA_F16(d, a, bd, id, en) do {                                      \
    uint32_t _e = (en);                                                        \
    asm volatile("{ .reg .pred p; setp.ne.u32 p, %4, 0;"                       \
        " tcgen05.mma.cta_group::1.kind::f16 [%0], [%1], %2, %3, {%5,%5,%5,%5}, p; }" \
        :: "r"(d), "r"(a), "l"(bd), "r"(id), "r"(_e), "r"(0u) : "memory");     \
} while (0)

__device__ __forceinline__ uint64_t make_desc(uint32_t a) {
    const uint64_t base = (2ull << 61) | (1ull << 46) | (64ull << 32) | (1ull << 16);
    return base | ((uint64_t)(a >> 4) & 0x3FFF);
}
// idesc: F32 accum, F16 inputs, N=128 (16<<17), M=128 (8<<24)
#define IDESC 0x8200010u
#endif  // HAS_TCGEN05

// ---------------- prep: LayerNorm ----------------
__global__ __launch_bounds__(256) void k_ln(const float* __restrict__ node,
                                            const float* __restrict__ lw,
                                            const float* __restrict__ lb) {
    int j = blockIdx.x, t = threadIdx.x;
    __shared__ float red[8];
    float v = node[j * DD + t];
    float x = v;
    #pragma unroll
    for (int o = 16; o > 0; o >>= 1) x += __shfl_xor_sync(0xffffffffu, x, o);
    if ((t & 31) == 0) red[t >> 5] = x;
    __syncthreads();
    float mu = 0.f;
    #pragma unroll
    for (int w = 0; w < 8; w++) mu += red[w];
    mu *= (1.0f / 256.0f);
    __syncthreads();
    float d = v - mu;
    x = d * d;
    #pragma unroll
    for (int o = 16; o > 0; o >>= 1) x += __shfl_xor_sync(0xffffffffu, x, o);
    if ((t & 31) == 0) red[t >> 5] = x;
    __syncthreads();
    float var = 0.f;
    #pragma unroll
    for (int w = 0; w < 8; w++) var += red[w];
    var *= (1.0f / 256.0f);
    float rs = rsqrtf(var + 1e-5f);
    g_s[j * DD + t] = d * rs * lw[t] + lb[t];
}

// ---------------- prep: w_p -> SW128 image + linear transpose ----------------
__global__ __launch_bounds__(256) void k_wp(const float* __restrict__ ow) {
    int idx = blockIdx.x * 256 + threadIdx.x;
    int e = idx >> 8, h = idx & 255;
    __half v = __float2half(ow[e * (2 * HH) + h]);
    uint32_t off = (uint32_t)(((h >> 6) * 16 + (e >> 3)) * 1024 + (e & 7) * 128 + (h & 63) * 2);
    off ^= (off >> 3) & 0x70;
    g_wpB[off >> 1] = v;
    g_wpT[h * EE + e] = v;
}

// ---------------- prep: proj GEMM ----------------
__global__ __launch_bounds__(128) void k_proj(const float* __restrict__ pw,
                                              const float* __restrict__ pb) {
    __shared__ float sA[32][33];
    __shared__ float sB[32][33];
    int t = threadIdx.x;
    int j0 = blockIdx.x * 32, h0 = blockIdx.y * 32;
    int ty = t >> 4, tx = t & 15;
    float acc[4][2] = {};
    for (int kc = 0; kc < DD; kc += 32) {
        __syncthreads();
        int r = t >> 2, c0 = (t & 3) * 8;
        float4 a0 = *(const float4*)(g_s + (size_t)(j0 + r) * DD + kc + c0);
        float4 a1 = *(const float4*)(g_s + (size_t)(j0 + r) * DD + kc + c0 + 4);
        sA[r][c0 + 0] = a0.x; sA[r][c0 + 1] = a0.y; sA[r][c0 + 2] = a0.z; sA[r][c0 + 3] = a0.w;
        sA[r][c0 + 4] = a1.x; sA[r][c0 + 5] = a1.y; sA[r][c0 + 6] = a1.z; sA[r][c0 + 7] = a1.w;
        float4 b0 = *(const float4*)(pw + (size_t)(h0 + r) * DD + kc + c0);
        float4 b1 = *(const float4*)(pw + (size_t)(h0 + r) * DD + kc + c0 + 4);
        sB[r][c0 + 0] = b0.x; sB[r][c0 + 1] = b0.y; sB[r][c0 + 2] = b0.z; sB[r][c0 + 3] = b0.w;
        sB[r][c0 + 4] = b1.x; sB[r][c0 + 5] = b1.y; sB[r][c0 + 6] = b1.z; sB[r][c0 + 7] = b1.w;
        __syncthreads();
        #pragma unroll
        for (int k = 0; k < 32; k++) {
            float bb0 = sB[tx * 2 + 0][k];
            float bb1 = sB[tx * 2 + 1][k];
            #pragma unroll
            for (int m = 0; m < 4; m++) {
                float a = sA[ty * 4 + m][k];
                acc[m][0] += a * bb0;
                acc[m][1] += a * bb1;
            }
        }
    }
    #pragma unroll
    for (int m = 0; m < 4; m++) {
        int j = j0 + ty * 4 + m;
        #pragma unroll
        for (int n = 0; n < 2; n++) {
            int h = h0 + tx * 2 + n;
            __half hv = __float2half(acc[m][n] + pb[h]);
            if (h < HH) g_qh[(size_t)j * HH + h] = hv;
            else        g_kh[(size_t)j * HH + (h - HH)] = hv;
        }
    }
}

// ---------------- prep: Aq / Bk' (4 rows per block, 256 threads, grid 128 x2 launches) ----
__global__ __launch_bounds__(256) void k_aqbk2(const float* __restrict__ ow,
                                               const float* __restrict__ ob, int roff) {
    __shared__ float sx[4][256];
    int t = threadIdx.x;
    int e = t & 127, rg = t >> 7;      // rg: rows {0,1} or {2,3}
    int r0 = roff + blockIdx.x * 4;
    #pragma unroll
    for (int u = 0; u < 4; u++) {
        int idx = u * 256 + t;
        int rr = idx >> 8, c = idx & 255;
        int gr = r0 + rr;
        const __half* src = (gr < NN) ? (g_qh + (size_t)gr * HH)
                                      : (g_kh + (size_t)(gr - NN) * HH);
        sx[rr][c] = __half2float(src[c]);
    }
    __syncthreads();
    const float* wv = ow + (size_t)e * (2 * HH) + HH;
    float a0 = 0.f, a1 = 0.f;
    #pragma unroll 8
    for (int h = 0; h < 256; h += 4) {
        float4 w4 = *(const float4*)(wv + h);
        float4 x0 = *(const float4*)&sx[rg * 2 + 0][h];
        float4 x1 = *(const float4*)&sx[rg * 2 + 1][h];
        a0 += x0.x * w4.x + x0.y * w4.y + x0.z * w4.z + x0.w * w4.w;
        a1 += x1.x * w4.x + x1.y * w4.y + x1.z * w4.z + x1.w * w4.w;
    }
    float obe = ob[e];
    int gr0 = r0 + rg * 2;
    if (gr0 < NN) {
        g_aq[(size_t)gr0 * EE + e] = a0;
        g_aq[(size_t)(gr0 + 1) * EE + e] = a1;
    } else {
        g_bkp[(size_t)(gr0 - NN) * EE + e] = obe - a0;
        g_bkp[(size_t)(gr0 + 1 - NN) * EE + e] = obe - a1;
    }
}

// ---------------- main kernel ----------------
// tcgen05 SMEM layout: tmem ptr @0, mbars @8/16; B image @1024; k rows; bk rows.
#define SB_OFF   1024
#define SK_OFF   (SB_OFF + 65536)         // 66560
#define SBK_OFF  (SK_OFF + TI * 512)      // 74752
#define SMEM_TC  (SBK_OFF + TI * 512)     // 82944

// wmma fallback layout:
#define FB_LDQ 272
#define FB_LDW 144
#define FB_SM_Q 0
#define FB_SM_B (128 * FB_LDQ * 2)
#define FB_SM_A (FB_SM_B + 256 * FB_LDW * 2)
#define FB_SM_K (FB_SM_A + 128 * FB_LDQ * 2)
#define FB_SM_BK (FB_SM_K + 512)
#define SMEM_FB (FB_SM_BK + 16 * 128 * 4)  // 221696

#define SMEM_LAUNCH ((SMEM_TC) > (SMEM_FB) ? (SMEM_TC) : (SMEM_FB))

__global__ __launch_bounds__(256, 1) void k_main(float* __restrict__ out) {
#if HAS_TCGEN05
    extern __shared__ char smem[];
    uint32_t sbase = smem_u32(smem);
    int t = threadIdx.x;
    int w = t >> 5;
    int r = t & 127;          // output row within j-tile == TMEM lane
    int ch = t >> 7;          // column half: 0 -> cols 0-63, 1 -> cols 64-127
    int j0 = blockIdx.x * TJ;
    int ibase = blockIdx.y * TI;

    uint32_t mb0 = sbase + 8, mb1 = sbase + 16;

    if (w == 0) { TC_ALLOC(sbase, 512); TC_RELINQ(); }
    if (t == 0) { MBAR_INIT(mb0, 1); MBAR_INIT(mb1, 1); }
    __syncthreads();
    uint32_t tmem;
    asm volatile("ld.shared.b32 %0, [%1];" : "=r"(tmem) : "r"(sbase));

    // ---- prologue loads ----
    #pragma unroll
    for (int u = 0; u < 16; u++) {                       // B image: 64KB
        int idx = u * 256 + t;
        *(int4*)(smem + SB_OFF + idx * 16) = *(const int4*)((const char*)g_wpB + idx * 16);
    }
    #pragma unroll
    for (int u = 0; u < 2; u++) {                        // k rows: 8KB
        int idx = u * 256 + t;
        int rr = idx >> 5, c = idx & 31;
        *(int4*)(smem + SK_OFF + idx * 16) = *(const int4*)(g_kh + (size_t)(ibase + rr) * HH + c * 8);
    }
    #pragma unroll
    for (int u = 0; u < 2; u++) {                        // bk rows: 8KB
        int idx = u * 256 + t;
        int rr = idx >> 5, c = idx & 31;
        *(int4*)(smem + SBK_OFF + idx * 16) = *(const int4*)(g_bkp + (size_t)(ibase + rr) * EE + c * 4);
    }
    // register caches: q half-row (256B) and aq half-row (256B)
    uint4 qv[16];
    float4 aqv[16];
    {
        const uint4* qsrc = (const uint4*)(g_qh + (size_t)(j0 + r) * HH + ch * 128);
        const float4* asrc = (const float4*)(g_aq + (size_t)(j0 + r) * EE + ch * 64);
        #pragma unroll
        for (int u = 0; u < 16; u++) qv[u] = qsrc[u];
        #pragma unroll
        for (int u = 0; u < 16; u++) aqv[u] = asrc[u];
    }
    __syncthreads();

    uint32_t warp_off = (uint32_t)((r >> 5) << 21);
    uint64_t bbase = make_desc(sbase + SB_OFF);

    for (int i = 0; i <= TI; i++) {
        if (i < TI) {
            // ---- build A'[b] = q .* k_i directly into TMEM ----
            int b = i & 1;
            const __half2* kr = (const __half2*)(smem + SK_OFF + i * 512) + ch * 64;
            uint32_t a_st = tmem + 256 + b * 128 + ch * 64 + warp_off;
            #pragma unroll
            for (int g = 0; g < 2; g++) {
                uint32_t regs[32];
                #pragma unroll
                for (int u = 0; u < 8; u++) {
                    uint4 q4 = qv[g * 8 + u];
                    const __half2* qh2 = (const __half2*)&q4;
                    #pragma unroll
                    for (int v2 = 0; v2 < 4; v2++) {
                        __half2 m = __hmul2(qh2[v2], kr[g * 32 + u * 4 + v2]);
                        regs[u * 4 + v2] = *(const uint32_t*)&m;
                    }
                }
                TC_ST_X32(a_st + g * 32, regs);
            }
            TC_WAIT_ST();
            TC_FENCE_BEFORE();
            __syncthreads();
            // ---- issue MMA(i) (async; overlaps epilogue(i-1) below) ----
            if (w == 0) {
                TC_FENCE_AFTER();
                if (elect_one()) {
                    uint32_t d_tm = tmem + b * 128;
                    uint32_t a_tm = tmem + 256 + b * 128;
                    #pragma unroll
                    for (int s = 0; s < 16; s++) {
                        uint64_t bd = bbase + (uint64_t)((s >> 2) * 1024 + (s & 3) * 2);
                        TC_MMA_F16(d_tm, a_tm + s * 8, bd, IDESC, (s > 0) ? 1u : 0u);
                    }
                    TC_COMMIT(b ? mb1 : mb0);
                }
            }
        }
        if (i >= 1) {
            // ---- epilogue(i-1) ----
            int ii = i - 1;
            int pb = ii & 1;
            MBAR_WAIT(pb ? mb1 : mb0, (ii >> 1) & 1);
            TC_FENCE_AFTER();
            uint32_t d_tm = tmem + pb * 128 + ch * 64;
            const float4* bkr = (const float4*)(smem + SBK_OFF + ii * 512) + ch * 16;
            float* op = out + (((size_t)(ibase + ii) * NN) + j0 + r) * EE + ch * 64;
            #pragma unroll
            for (int g = 0; g < 2; g++) {
                uint32_t dr[32];
                TC_LD_X32(dr, d_tm + g * 32);
                TC_WAIT_LD();
                #pragma unroll
                for (int u = 0; u < 8; u++) {
                    float4 a = aqv[g * 8 + u];
                    float4 bv = bkr[g * 8 + u];
                    float4 o;
                    o.x = __uint_as_float(dr[u * 4 + 0]) + a.x + bv.x;
                    o.y = __uint_as_float(dr[u * 4 + 1]) + a.y + bv.y;
                    o.z = __uint_as_float(dr[u * 4 + 2]) + a.z + bv.z;
                    o.w = __uint_as_float(dr[u * 4 + 3]) + a.w + bv.w;
                    *(float4*)(op + g * 32 + u * 4) = o;
                }
            }
        }
    }

    __syncthreads();
    if (t == 0) { MBAR_INVAL(mb0); MBAR_INVAL(mb1); }
    __syncthreads();
    if (w == 0) { TC_DEALLOC(tmem, 512); }
#else
    // -------- wmma fallback (family-generic pass) --------
    using namespace nvcuda;
    extern __shared__ char smem_raw[];
    __half* sQ  = (__half*)(smem_raw + FB_SM_Q);
    __half* sB  = (__half*)(smem_raw + FB_SM_B);
    __half* sA  = (__half*)(smem_raw + FB_SM_A);
    __half* sK  = (__half*)(smem_raw + FB_SM_K);
    float*  sBk = (float*)(smem_raw + FB_SM_BK);

    int t = threadIdx.x;
    int w = t >> 5;
    int wj = w >> 1;
    int we = w & 1;
    int j0 = blockIdx.x * TJ;
    int ibase = blockIdx.y * TI;

    for (int idx = t; idx < 4096; idx += 256) {
        int r = idx >> 5, c = idx & 31;
        *(int4*)(sQ + r * FB_LDQ + c * 8) = *(const int4*)(g_qh + (size_t)(j0 + r) * HH + c * 8);
    }
    for (int idx = t; idx < 4096; idx += 256) {
        int r = idx >> 4, c = idx & 15;
        *(int4*)(sB + r * FB_LDW + c * 8) = *(const int4*)(g_wpT + (size_t)r * EE + c * 8);
    }

    for (int it = 0; it < TI; it++) {
        int i = ibase + it;
        if (t < 32) *(int4*)(sK + t * 8) = *(const int4*)(g_kh + (size_t)i * HH + t * 8);
        {
            const float4* src = (const float4*)(g_bkp + (size_t)i * EE);
            #pragma unroll
            for (int idx = t; idx < 512; idx += 256) {
                int c = idx & 31;
                ((float4*)sBk)[idx] = src[c];
            }
        }
        __syncthreads();

        for (int idx = t; idx < 4096; idx += 256) {
            int r = idx >> 5, c = idx & 31;
            int4 qv = *(const int4*)(sQ + r * FB_LDQ + c * 8);
            int4 kv = *(const int4*)(sK + c * 8);
            const __half2* qh2 = (const __half2*)&qv;
            const __half2* kh2 = (const __half2*)&kv;
            int4 av;
            __half2* ah = (__half2*)&av;
            ah[0] = __hmul2(qh2[0], kh2[0]);
            ah[1] = __hmul2(qh2[1], kh2[1]);
            ah[2] = __hmul2(qh2[2], kh2[2]);
            ah[3] = __hmul2(qh2[3], kh2[3]);
            *(int4*)(sA + r * FB_LDQ + c * 8) = av;
        }
        __syncthreads();

        wmma::fragment<wmma::accumulator, 16, 16, 16, float> acc[2][4];
        #pragma unroll
        for (int m = 0; m < 2; m++)
            #pragma unroll
            for (int n = 0; n < 4; n++)
                wmma::fill_fragment(acc[m][n], 0.0f);

        #pragma unroll
        for (int kk = 0; kk < HH; kk += 16) {
            wmma::fragment<wmma::matrix_a, 16, 16, 16, __half, wmma::row_major> af[2];
            wmma::fragment<wmma::matrix_b, 16, 16, 16, __half, wmma::row_major> bf[4];
            #pragma unroll
            for (int m = 0; m < 2; m++)
                wmma::load_matrix_sync(af[m], sA + (wj * 32 + m * 16) * FB_LDQ + kk, FB_LDQ);
            #pragma unroll
            for (int n = 0; n < 4; n++)
                wmma::load_matrix_sync(bf[n], sB + kk * FB_LDW + we * 64 + n * 16, FB_LDW);
            #pragma unroll
            for (int m = 0; m < 2; m++)
                #pragma unroll
                for (int n = 0; n < 4; n++)
                    wmma::mma_sync(acc[m][n], af[m], bf[n], acc[m][n]);
        }

        #pragma unroll
        for (int m = 0; m < 2; m++) {
            int jr = j0 + wj * 32 + m * 16;
            #pragma unroll
            for (int n = 0; n < 4; n++) {
                int ec = we * 64 + n * 16;
                wmma::fragment<wmma::accumulator, 16, 16, 16, float> aqf, bkf;
                wmma::load_matrix_sync(aqf, g_aq + (size_t)jr * EE + ec, EE, wmma::mem_row_major);
                wmma::load_matrix_sync(bkf, sBk + ec, 128, wmma::mem_row_major);
                #pragma unroll
                for (int u = 0; u < acc[m][n].num_elements; u++)
                    acc[m][n].x[u] += aqf.x[u] + bkf.x[u];
                wmma::store_matrix_sync(out + ((size_t)i * NN + jr) * EE + ec,
                                        acc[m][n], EE, wmma::mem_row_major);
            }
        }
        __syncthreads();
    }
#endif
}

// ---------------- launcher (6 launches; k_main is #6 -> ncu -s5 -c1 captures it) ----
extern "C" void kernel_launch(void* const* d_in, const int* in_sizes, int n_in,
                              void* d_out, int out_size) {
    const float* node = (const float*)d_in[0];
    const float* ln_w = (const float*)d_in[1];
    const float* ln_b = (const float*)d_in[2];
    const float* pw   = (const float*)d_in[3];
    const float* pb   = (const float*)d_in[4];
    const float* ow   = (const float*)d_in[5];
    const float* ob   = (const float*)d_in[6];
    float* out = (float*)d_out;

    cudaFuncSetAttribute(k_main, cudaFuncAttributeMaxDynamicSharedMemorySize, SMEM_LAUNCH);

    k_ln<<<NN, 256>>>(node, ln_w, ln_b);
    k_wp<<<128, 256>>>(ow);
    {
        dim3 g(NN / 32, (2 * HH) / 32);
        k_proj<<<g, 128>>>(pw, pb);
    }
    k_aqbk2<<<128, 256>>>(ow, ob, 0);      // aq  (q rows 0-511)
    k_aqbk2<<<128, 256>>>(ow, ob, 512);    // bk' (k rows 512-1023)
    {
        dim3 g(NN / TJ, NN / TI);
        k_main<<<g, 256, SMEM_LAUNCH>>>(out);
    }
}

// round 6
// speedup vs baseline: 1.4236x; 1.4236x over previous
#include <cuda_runtime.h>
#include <cuda_fp16.h>
#include <mma.h>
#include <cstdint>

#define NN 512
#define DD 256
#define HH 256
#define EE 128
#define TJ 128
#define TI 16

#if defined(__CUDA_ARCH__) && (defined(__CUDA_ARCH_FEAT_SM103_ALL) || defined(__CUDA_ARCH_FEAT_SM100_ALL) || defined(__CUDA_ARCH_SPECIFIC__))
#define HAS_TCGEN05 1
#else
#define HAS_TCGEN05 0
#endif

// ---------------- static device scratch ----------------
__device__ __align__(128) float  g_s[NN * DD];
__device__ __align__(128) __half g_qh[NN * HH];
__device__ __align__(128) __half g_kh[NN * HH];
__device__ __align__(128) __half g_wpB[HH * EE];    // w_p SW128 blocked-atom image
__device__ __align__(128) __half g_wpT[HH * EE];    // w_p [h][e] (wmma fallback)
__device__ __align__(128) float  g_wdT[HH * EE];    // w_d transposed [h][e] fp32
__device__ __align__(128) float  g_aq[NN * EE];
__device__ __align__(128) float  g_bkp[NN * EE];

// ---------------- PTX helpers ----------------
__device__ __forceinline__ uint32_t smem_u32(const void* p) {
    uint32_t a;
    asm("{ .reg .u64 t; cvta.to.shared.u64 t, %1; cvt.u32.u64 %0, t; }" : "=r"(a) : "l"(p));
    return a;
}

#if HAS_TCGEN05
__device__ __forceinline__ uint32_t elect_one() {
    uint32_t p;
    asm volatile("{ .reg .pred p; elect.sync _|p, 0xFFFFFFFF; selp.b32 %0, 1, 0, p; }" : "=r"(p));
    return p;
}
#define TC_ALLOC(dst, n) \
    asm volatile("tcgen05.alloc.cta_group::1.sync.aligned.shared::cta.b32 [%0], %1;" \
                 :: "r"(dst), "r"(n) : "memory")
#define TC_RELINQ() \
    asm volatile("tcgen05.relinquish_alloc_permit.cta_group::1.sync.aligned;")
#define TC_DEALLOC(base, n) \
    asm volatile("tcgen05.dealloc.cta_group::1.sync.aligned.b32 %0, %1;" :: "r"(base), "r"(n))
#define TC_WAIT_ST() asm volatile("tcgen05.wait::st.sync.aligned;" ::: "memory")
#define TC_WAIT_LD() asm volatile("tcgen05.wait::ld.sync.aligned;" ::: "memory")
#define TC_FENCE_BEFORE() asm volatile("tcgen05.fence::before_thread_sync;" ::: "memory")
#define TC_FENCE_AFTER()  asm volatile("tcgen05.fence::after_thread_sync;" ::: "memory")
#define TC_COMMIT(mbar) \
    asm volatile("tcgen05.commit.cta_group::1.mbarrier::arrive::one.shared::cluster.b64 [%0];" \
                 :: "r"(mbar) : "memory")
#define MBAR_INIT(a, c) \
    asm volatile("mbarrier.init.shared.b64 [%0], %1;" :: "r"(a), "r"(c) : "memory")
#define MBAR_INVAL(a) \
    asm volatile("mbarrier.inval.shared.b64 [%0];" :: "r"(a) : "memory")

#define MBAR_WAIT(mbar, par) do {                                              \
    uint32_t _m = (mbar), _p = (par), _d;                                      \
    asm volatile("{ .reg .pred p; mbarrier.try_wait.parity.acquire.cta.shared::cta.b64 p, [%1], %2; selp.b32 %0, 1, 0, p; }" \
        : "=r"(_d) : "r"(_m), "r"(_p) : "memory");                             \
    if (!_d) {                                                                 \
        asm volatile("{ .reg .pred P1; WL_%=: mbarrier.try_wait.parity.acquire.cta.shared::cta.b64 P1, [%0], %1, 0x989680; @P1 bra.uni WD_%=; bra.uni WL_%=; WD_%=: }" \
            :: "r"(_m), "r"(_p) : "memory");                                   \
    }                                                                          \
} while (0)

#define TC_ST_X32(addr, r)                                                     \
    asm volatile("tcgen05.st.sync.aligned.32x32b.x32.b32 [%0], "               \
        "{%1,%2,%3,%4,%5,%6,%7,%8,%9,%10,%11,%12,%13,%14,%15,%16,"            \
        "%17,%18,%19,%20,%21,%22,%23,%24,%25,%26,%27,%28,%29,%30,%31,%32};"    \
        :: "r"(addr),                                                          \
        "r"((r)[0]),"r"((r)[1]),"r"((r)[2]),"r"((r)[3]),"r"((r)[4]),"r"((r)[5]),"r"((r)[6]),"r"((r)[7]), \
        "r"((r)[8]),"r"((r)[9]),"r"((r)[10]),"r"((r)[11]),"r"((r)[12]),"r"((r)[13]),"r"((r)[14]),"r"((r)[15]), \
        "r"((r)[16]),"r"((r)[17]),"r"((r)[18]),"r"((r)[19]),"r"((r)[20]),"r"((r)[21]),"r"((r)[22]),"r"((r)[23]), \
        "r"((r)[24]),"r"((r)[25]),"r"((r)[26]),"r"((r)[27]),"r"((r)[28]),"r"((r)[29]),"r"((r)[30]),"r"((r)[31]) \
        : "memory")

#define TC_LD_X32(r, addr)                                                     \
    asm volatile("tcgen05.ld.sync.aligned.32x32b.x32.b32 "                     \
        "{%0,%1,%2,%3,%4,%5,%6,%7,%8,%9,%10,%11,%12,%13,%14,%15,"             \
        "%16,%17,%18,%19,%20,%21,%22,%23,%24,%25,%26,%27,%28,%29,%30,%31}, [%32];" \
        : "=r"((r)[0]),"=r"((r)[1]),"=r"((r)[2]),"=r"((r)[3]),"=r"((r)[4]),"=r"((r)[5]),"=r"((r)[6]),"=r"((r)[7]), \
          "=r"((r)[8]),"=r"((r)[9]),"=r"((r)[10]),"=r"((r)[11]),"=r"((r)[12]),"=r"((r)[13]),"=r"((r)[14]),"=r"((r)[15]), \
          "=r"((r)[16]),"=r"((r)[17]),"=r"((r)[18]),"=r"((r)[19]),"=r"((r)[20]),"=r"((r)[21]),"=r"((r)[22]),"=r"((r)[23]), \
          "=r"((r)[24]),"=r"((r)[25]),"=r"((r)[26]),"=r"((r)[27]),"=r"((r)[28]),"=r"((r)[29]),"=r"((r)[30]),"=r"((r)[31]) \
        : "r"(addr))

#define TC_MMA_F16(d, a, bd, id, en) do {                                      \
    uint32_t _e = (en);                                                        \
    asm volatile("{ .reg .pred p; setp.ne.u32 p, %4, 0;"                       \
        " tcgen05.mma.cta_group::1.kind::f16 [%0], [%1], %2, %3, {%5,%5,%5,%5}, p; }" \
        :: "r"(d), "r"(a), "l"(bd), "r"(id), "r"(_e), "r"(0u) : "memory");     \
} while (0)

__device__ __forceinline__ uint64_t make_desc(uint32_t a) {
    const uint64_t base = (2ull << 61) | (1ull << 46) | (64ull << 32) | (1ull << 16);
    return base | ((uint64_t)(a >> 4) & 0x3FFF);
}
#define IDESC 0x8200010u
#endif  // HAS_TCGEN05

// ---------------- prep: LayerNorm ----------------
__global__ __launch_bounds__(256) void k_ln(const float* __restrict__ node,
                                            const float* __restrict__ lw,
                                            const float* __restrict__ lb) {
    int j = blockIdx.x, t = threadIdx.x;
    __shared__ float red[8];
    float v = node[j * DD + t];
    float x = v;
    #pragma unroll
    for (int o = 16; o > 0; o >>= 1) x += __shfl_xor_sync(0xffffffffu, x, o);
    if ((t & 31) == 0) red[t >> 5] = x;
    __syncthreads();
    float mu = 0.f;
    #pragma unroll
    for (int w = 0; w < 8; w++) mu += red[w];
    mu *= (1.0f / 256.0f);
    __syncthreads();
    float d = v - mu;
    x = d * d;
    #pragma unroll
    for (int o = 16; o > 0; o >>= 1) x += __shfl_xor_sync(0xffffffffu, x, o);
    if ((t & 31) == 0) red[t >> 5] = x;
    __syncthreads();
    float var = 0.f;
    #pragma unroll
    for (int w = 0; w < 8; w++) var += red[w];
    var *= (1.0f / 256.0f);
    float rs = rsqrtf(var + 1e-5f);
    g_s[j * DD + t] = d * rs * lw[t] + lb[t];
}

// ---------------- prep: weight images (wpB SW128, wpT fallback, wdT transposed) ----
__global__ __launch_bounds__(256) void k_wp(const float* __restrict__ ow) {
    int bx = blockIdx.x, t = threadIdx.x;
    if (bx < 128) {
        int idx = bx * 256 + t;                 // 0..32767
        int e = idx >> 8, h = idx & 255;
        __half v = __float2half(ow[e * (2 * HH) + h]);
        uint32_t off = (uint32_t)(((h >> 6) * 16 + (e >> 3)) * 1024 + (e & 7) * 128 + (h & 63) * 2);
        off ^= (off >> 3) & 0x70;
        g_wpB[off >> 1] = v;
        g_wpT[h * EE + e] = v;
    } else {
        int idx = (bx - 128) * 256 + t;         // 0..32767
        int h = idx >> 7, e = idx & 127;
        g_wdT[h * EE + e] = ow[e * (2 * HH) + HH + h];   // w_d transposed, coalesced stores
    }
}

// ---------------- prep: proj GEMM (64j x 32h tile, 256 thr, grid 8x16) ----------------
__global__ __launch_bounds__(256) void k_proj(const float* __restrict__ pw,
                                              const float* __restrict__ pb) {
    __shared__ float sA[64][33];
    __shared__ float sB[32][33];
    int t = threadIdx.x;
    int j0 = blockIdx.x * 64, h0 = blockIdx.y * 32;
    int ty = t >> 4, tx = t & 15;
    float acc[4][2] = {};
    for (int kc = 0; kc < DD; kc += 32) {
        __syncthreads();
        #pragma unroll
        for (int u = 0; u < 2; u++) {
            int idx = u * 256 + t;
            int r = idx >> 3, c4 = (idx & 7) * 4;
            float4 v = *(const float4*)(g_s + (size_t)(j0 + r) * DD + kc + c4);
            sA[r][c4 + 0] = v.x; sA[r][c4 + 1] = v.y; sA[r][c4 + 2] = v.z; sA[r][c4 + 3] = v.w;
        }
        {
            int r = t >> 3, c4 = (t & 7) * 4;
            if (r < 32) {
                float4 v = *(const float4*)(pw + (size_t)(h0 + r) * DD + kc + c4);
                sB[r][c4 + 0] = v.x; sB[r][c4 + 1] = v.y; sB[r][c4 + 2] = v.z; sB[r][c4 + 3] = v.w;
            }
        }
        __syncthreads();
        #pragma unroll
        for (int k = 0; k < 32; k++) {
            float b0 = sB[tx * 2 + 0][k];
            float b1 = sB[tx * 2 + 1][k];
            #pragma unroll
            for (int m = 0; m < 4; m++) {
                float a = sA[ty * 4 + m][k];
                acc[m][0] += a * b0;
                acc[m][1] += a * b1;
            }
        }
    }
    #pragma unroll
    for (int m = 0; m < 4; m++) {
        int j = j0 + ty * 4 + m;
        #pragma unroll
        for (int n = 0; n < 2; n++) {
            int h = h0 + tx * 2 + n;
            __half hv = __float2half(acc[m][n] + pb[h]);
            if (h < HH) g_qh[(size_t)j * HH + h] = hv;
            else        g_kh[(size_t)j * HH + (h - HH)] = hv;
        }
    }
}

// ---------------- prep: Aq / Bk' — coalesced via g_wdT (grid 256, 4 rows/block) ----
__global__ __launch_bounds__(256) void k_aqbk3(const float* __restrict__ ob) {
    __shared__ float sx[4][256];
    int t = threadIdx.x;
    int e = t & 127, rg = t >> 7;
    int r0 = blockIdx.x * 4;
    #pragma unroll
    for (int u = 0; u < 2; u++) {
        int idx = u * 256 + t;                 // 0..511 half2 units
        int rr = idx >> 7, c2 = idx & 127;
        int gr = r0 + rr;
        const __half2* src = (gr < NN) ? (const __half2*)(g_qh + (size_t)gr * HH)
                                       : (const __half2*)(g_kh + (size_t)(gr - NN) * HH);
        float2 v = __half22float2(src[c2]);
        sx[rr][c2 * 2 + 0] = v.x;
        sx[rr][c2 * 2 + 1] = v.y;
    }
    __syncthreads();
    const float* x0 = sx[rg * 2 + 0];
    const float* x1 = sx[rg * 2 + 1];
    float a0 = 0.f, a1 = 0.f;
    #pragma unroll 8
    for (int h = 0; h < 256; h++) {
        float w = g_wdT[h * EE + e];           // lanes -> consecutive e: coalesced
        a0 += x0[h] * w;
        a1 += x1[h] * w;
    }
    float obe = ob[e];
    int gr0 = r0 + rg * 2;
    if (gr0 < NN) {
        g_aq[(size_t)gr0 * EE + e] = a0;
        g_aq[(size_t)(gr0 + 1) * EE + e] = a1;
    } else {
        g_bkp[(size_t)(gr0 - NN) * EE + e] = obe - a0;
        g_bkp[(size_t)(gr0 + 1 - NN) * EE + e] = obe - a1;
    }
}

// ---------------- main kernel ----------------
// SMEM layout: misc @0 (tmem ptr, mbars @8/16); B @1024 (64K);
// sD @66560 (64K + 2K slack; doubles as q staging w/ stride 528);
// aq @134144 (64K); k @199680 (8K); bk @207872 (8K). total 216064
#define SB_OFF   1024
#define SD_OFF   66560
#define AQ_OFF   134144
#define SK_OFF   199680
#define SBK_OFF  207872
#define SMEM_TC  216064

#define FB_LDQ 272
#define FB_LDW 144
#define FB_SM_Q 0
#define FB_SM_B (128 * FB_LDQ * 2)
#define FB_SM_A (FB_SM_B + 256 * FB_LDW * 2)
#define FB_SM_K (FB_SM_A + 128 * FB_LDQ * 2)
#define FB_SM_BK (FB_SM_K + 512)
#define SMEM_FB (FB_SM_BK + 16 * 128 * 4)  // 221696

#define SMEM_LAUNCH ((SMEM_TC) > (SMEM_FB) ? (SMEM_TC) : (SMEM_FB))

__global__ __launch_bounds__(256, 1) void k_main(float* __restrict__ out) {
#if HAS_TCGEN05
    extern __shared__ char smem[];
    uint32_t sbase = smem_u32(smem);
    int t = threadIdx.x;
    int w = t >> 5;
    int r = t & 127;          // TMEM lane = j-row in tile
    int ch = t >> 7;          // 64-col half
    int j0 = blockIdx.x * TJ;
    int ibase = blockIdx.y * TI;

    uint32_t mb0 = sbase + 8, mb1 = sbase + 16;

    if (w == 0) { TC_ALLOC(sbase, 512); TC_RELINQ(); }
    if (t == 0) { MBAR_INIT(mb0, 1); MBAR_INIT(mb1, 1); }
    __syncthreads();
    uint32_t tmem;
    asm volatile("ld.shared.b32 %0, [%1];" : "=r"(tmem) : "r"(sbase));

    // ---- prologue: all staging coalesced ----
    #pragma unroll
    for (int u = 0; u < 16; u++) {            // q -> sD staging (stride 528)
        int idx = u * 256 + t;
        int rr = idx >> 5, c = idx & 31;
        *(int4*)(smem + SD_OFF + rr * 528 + c * 16) =
            *(const int4*)(g_qh + (size_t)(j0 + rr) * HH + c * 8);
    }
    #pragma unroll
    for (int u = 0; u < 16; u++) {            // aq tile
        int idx = u * 256 + t;
        int rr = idx >> 5, c = idx & 31;
        *(int4*)(smem + AQ_OFF + rr * 512 + c * 16) =
            *(const int4*)(g_aq + (size_t)(j0 + rr) * EE + c * 4);
    }
    #pragma unroll
    for (int u = 0; u < 16; u++) {            // B image
        int idx = u * 256 + t;
        *(int4*)(smem + SB_OFF + idx * 16) = *(const int4*)((const char*)g_wpB + idx * 16);
    }
    #pragma unroll
    for (int u = 0; u < 2; u++) {             // k rows
        int idx = u * 256 + t;
        int rr = idx >> 5, c = idx & 31;
        *(int4*)(smem + SK_OFF + idx * 16) = *(const int4*)(g_kh + (size_t)(ibase + rr) * HH + c * 8);
    }
    #pragma unroll
    for (int u = 0; u < 2; u++) {             // bk rows
        int idx = u * 256 + t;
        int rr = idx >> 5, c = idx & 31;
        *(int4*)(smem + SBK_OFF + idx * 16) = *(const int4*)(g_bkp + (size_t)(ibase + rr) * EE + c * 4);
    }
    __syncthreads();
    // q half-row -> registers (one-time, 4-way LDS conflicts OK)
    int4 qv[16];
    #pragma unroll
    for (int cc = 0; cc < 16; cc++)
        qv[cc] = *(const int4*)(smem + SD_OFF + r * 528 + ch * 256 + cc * 16);
    __syncthreads();

    uint32_t warp_off = (uint32_t)((r >> 5) << 21);
    uint64_t bbase = make_desc(sbase + SB_OFF);

    for (int i = 0; i <= TI; i++) {
        if (i < TI) {
            // ---- build A'(i) -> TMEM ----
            int b = i & 1;
            const char* kbase = smem + SK_OFF + i * 512 + ch * 256;
            uint32_t a_st = tmem + 256 + b * 128 + ch * 64 + warp_off;
            #pragma unroll
            for (int g = 0; g < 2; g++) {
                uint32_t regs[32];
                #pragma unroll
                for (int u = 0; u < 8; u++) {
                    int4 q4 = qv[g * 8 + u];
                    int4 k4 = *(const int4*)(kbase + g * 128 + u * 16);
                    const __half2* qh2 = (const __half2*)&q4;
                    const __half2* kh2 = (const __half2*)&k4;
                    #pragma unroll
                    for (int v2 = 0; v2 < 4; v2++) {
                        __half2 m = __hmul2(qh2[v2], kh2[v2]);
                        regs[u * 4 + v2] = *(const uint32_t*)&m;
                    }
                }
                TC_ST_X32(a_st + g * 32, regs);
            }
            TC_WAIT_ST();
            TC_FENCE_BEFORE();
            __syncthreads();
            // ---- issue MMA(i) ----
            if (w == 0) {
                TC_FENCE_AFTER();
                if (elect_one()) {
                    uint32_t d_tm = tmem + b * 128;
                    uint32_t a_tm = tmem + 256 + b * 128;
                    #pragma unroll
                    for (int s = 0; s < 16; s++) {
                        uint64_t bd = bbase + (uint64_t)((s >> 2) * 1024 + (s & 3) * 2);
                        TC_MMA_F16(d_tm, a_tm + s * 8, bd, IDESC, (s > 0) ? 1u : 0u);
                    }
                    TC_COMMIT(b ? mb1 : mb0);
                }
            }
        }
        if (i >= 1) {
            // ---- epilogue(i-1): LDTM -> rotated SMEM -> coalesced STG ----
            int ii = i - 1;
            int pb2 = ii & 1;
            MBAR_WAIT(pb2 ? mb1 : mb0, (ii >> 1) & 1);
            TC_FENCE_AFTER();
            uint32_t d_tm = tmem + pb2 * 128 + ch * 64 + warp_off;
            // writer: lane = row r; chunk c stored at physical slot (c + r) & 31
            #pragma unroll
            for (int g = 0; g < 2; g++) {
                uint32_t dr[32];
                TC_LD_X32(dr, d_tm + g * 32);
                TC_WAIT_LD();
                #pragma unroll
                for (int cc = 0; cc < 8; cc++) {
                    int c = ch * 16 + g * 8 + cc;
                    uint32_t soff = (uint32_t)(SD_OFF + r * 512 + (((c + r) & 31) << 4));
                    *(float4*)(smem + soff) = *(const float4*)&dr[cc * 4];
                }
            }
            __syncthreads();
            // reader: warp -> 16 j-rows; lanes -> e chunks (coalesced everywhere)
            int l = t & 31;
            float4 bk4 = *(const float4*)(smem + SBK_OFF + ii * 512 + l * 16);
            float* obase = out + ((size_t)(ibase + ii) * NN + j0) * EE;
            #pragma unroll
            for (int jr = 0; jr < 16; jr++) {
                int j = w * 16 + jr;
                float4 d4 = *(const float4*)(smem + SD_OFF + j * 512 + (((l + j) & 31) << 4));
                float4 a4 = *(const float4*)(smem + AQ_OFF + j * 512 + l * 16);
                float4 o;
                o.x = d4.x + a4.x + bk4.x;
                o.y = d4.y + a4.y + bk4.y;
                o.z = d4.z + a4.z + bk4.z;
                o.w = d4.w + a4.w + bk4.w;
                *(float4*)(obase + (size_t)j * EE + l * 4) = o;
            }
        }
    }

    __syncthreads();
    if (t == 0) { MBAR_INVAL(mb0); MBAR_INVAL(mb1); }
    __syncthreads();
    if (w == 0) { TC_DEALLOC(tmem, 512); }
#else
    // -------- wmma fallback (family-generic pass) --------
    using namespace nvcuda;
    extern __shared__ char smem_raw[];
    __half* sQ  = (__half*)(smem_raw + FB_SM_Q);
    __half* sB  = (__half*)(smem_raw + FB_SM_B);
    __half* sA  = (__half*)(smem_raw + FB_SM_A);
    __half* sK  = (__half*)(smem_raw + FB_SM_K);
    float*  sBk = (float*)(smem_raw + FB_SM_BK);

    int t = threadIdx.x;
    int w = t >> 5;
    int wj = w >> 1;
    int we = w & 1;
    int j0 = blockIdx.x * TJ;
    int ibase = blockIdx.y * TI;

    for (int idx = t; idx < 4096; idx += 256) {
        int r = idx >> 5, c = idx & 31;
        *(int4*)(sQ + r * FB_LDQ + c * 8) = *(const int4*)(g_qh + (size_t)(j0 + r) * HH + c * 8);
    }
    for (int idx = t; idx < 4096; idx += 256) {
        int r = idx >> 4, c = idx & 15;
        *(int4*)(sB + r * FB_LDW + c * 8) = *(const int4*)(g_wpT + (size_t)r * EE + c * 8);
    }

    for (int it = 0; it < TI; it++) {
        int i = ibase + it;
        if (t < 32) *(int4*)(sK + t * 8) = *(const int4*)(g_kh + (size_t)i * HH + t * 8);
        {
            const float4* src = (const float4*)(g_bkp + (size_t)i * EE);
            #pragma unroll
            for (int idx = t; idx < 512; idx += 256) {
                int c = idx & 31;
                ((float4*)sBk)[idx] = src[c];
            }
        }
        __syncthreads();

        for (int idx = t; idx < 4096; idx += 256) {
            int r = idx >> 5, c = idx & 31;
            int4 qv = *(const int4*)(sQ + r * FB_LDQ + c * 8);
            int4 kv = *(const int4*)(sK + c * 8);
            const __half2* qh2 = (const __half2*)&qv;
            const __half2* kh2 = (const __half2*)&kv;
            int4 av;
            __half2* ah = (__half2*)&av;
            ah[0] = __hmul2(qh2[0], kh2[0]);
            ah[1] = __hmul2(qh2[1], kh2[1]);
            ah[2] = __hmul2(qh2[2], kh2[2]);
            ah[3] = __hmul2(qh2[3], kh2[3]);
            *(int4*)(sA + r * FB_LDQ + c * 8) = av;
        }
        __syncthreads();

        wmma::fragment<wmma::accumulator, 16, 16, 16, float> acc[2][4];
        #pragma unroll
        for (int m = 0; m < 2; m++)
            #pragma unroll
            for (int n = 0; n < 4; n++)
                wmma::fill_fragment(acc[m][n], 0.0f);

        #pragma unroll
        for (int kk = 0; kk < HH; kk += 16) {
            wmma::fragment<wmma::matrix_a, 16, 16, 16, __half, wmma::row_major> af[2];
            wmma::fragment<wmma::matrix_b, 16, 16, 16, __half, wmma::row_major> bf[4];
            #pragma unroll
            for (int m = 0; m < 2; m++)
                wmma::load_matrix_sync(af[m], sA + (wj * 32 + m * 16) * FB_LDQ + kk, FB_LDQ);
            #pragma unroll
            for (int n = 0; n < 4; n++)
                wmma::load_matrix_sync(bf[n], sB + kk * FB_LDW + we * 64 + n * 16, FB_LDW);
            #pragma unroll
            for (int m = 0; m < 2; m++)
                #pragma unroll
                for (int n = 0; n < 4; n++)
                    wmma::mma_sync(acc[m][n], af[m], bf[n], acc[m][n]);
        }

        #pragma unroll
        for (int m = 0; m < 2; m++) {
            int jr = j0 + wj * 32 + m * 16;
            #pragma unroll
            for (int n = 0; n < 4; n++) {
                int ec = we * 64 + n * 16;
                wmma::fragment<wmma::accumulator, 16, 16, 16, float> aqf, bkf;
                wmma::load_matrix_sync(aqf, g_aq + (size_t)jr * EE + ec, EE, wmma::mem_row_major);
                wmma::load_matrix_sync(bkf, sBk + ec, 128, wmma::mem_row_major);
                #pragma unroll
                for (int u = 0; u < acc[m][n].num_elements; u++)
                    acc[m][n].x[u] += aqf.x[u] + bkf.x[u];
                wmma::store_matrix_sync(out + ((size_t)i * NN + jr) * EE + ec,
                                        acc[m][n], EE, wmma::mem_row_major);
            }
        }
        __syncthreads();
    }
#endif
}

// ---------------- launcher ----------------
extern "C" void kernel_launch(void* const* d_in, const int* in_sizes, int n_in,
                              void* d_out, int out_size) {
    const float* node = (const float*)d_in[0];
    const float* ln_w = (const float*)d_in[1];
    const float* ln_b = (const float*)d_in[2];
    const float* pw   = (const float*)d_in[3];
    const float* pb   = (const float*)d_in[4];
    const float* ow   = (const float*)d_in[5];
    const float* ob   = (const float*)d_in[6];
    float* out = (float*)d_out;

    cudaFuncSetAttribute(k_main, cudaFuncAttributeMaxDynamicSharedMemorySize, SMEM_LAUNCH);

    k_ln<<<NN, 256>>>(node, ln_w, ln_b);
    k_wp<<<256, 256>>>(ow);
    {
        dim3 g(NN / 64, (2 * HH) / 32);
        k_proj<<<g, 256>>>(pw, pb);
    }
    k_aqbk3<<<2 * NN / 4, 256>>>(ob);
    {
        dim3 g(NN / TJ, NN / TI);
        k_main<<<g, 256, SMEM_LAUNCH>>>(out);
    }
}

// round 7
// speedup vs baseline: 1.5146x; 1.0639x over previous
#include <cuda_runtime.h>
#include <cuda_fp16.h>
#include <mma.h>
#include <cstdint>

#define NN 512
#define DD 256
#define HH 256
#define EE 128
#define TJ 128
#define TI 16

#if defined(__CUDA_ARCH__) && (defined(__CUDA_ARCH_FEAT_SM103_ALL) || defined(__CUDA_ARCH_FEAT_SM100_ALL) || defined(__CUDA_ARCH_SPECIFIC__))
#define HAS_TCGEN05 1
#else
#define HAS_TCGEN05 0
#endif

// ---------------- static device scratch ----------------
__device__ __align__(128) float  g_s[NN * DD];
__device__ __align__(128) __half g_qh[NN * HH];
__device__ __align__(128) __half g_kh[NN * HH];
__device__ __align__(128) __half g_wpB[HH * EE];    // w_p SW128 blocked-atom image
__device__ __align__(128) __half g_wpT[HH * EE];    // w_p [h][e] (wmma fallback)
__device__ __align__(128) float  g_wdT[HH * EE];    // w_d transposed [h][e] fp32
__device__ __align__(128) float  g_aq[NN * EE];
__device__ __align__(128) float  g_bkp[NN * EE];

// ---------------- PTX helpers ----------------
__device__ __forceinline__ uint32_t smem_u32(const void* p) {
    uint32_t a;
    asm("{ .reg .u64 t; cvta.to.shared.u64 t, %1; cvt.u32.u64 %0, t; }" : "=r"(a) : "l"(p));
    return a;
}

#if HAS_TCGEN05
__device__ __forceinline__ uint32_t elect_one() {
    uint32_t p;
    asm volatile("{ .reg .pred p; elect.sync _|p, 0xFFFFFFFF; selp.b32 %0, 1, 0, p; }" : "=r"(p));
    return p;
}
#define TC_ALLOC(dst, n) \
    asm volatile("tcgen05.alloc.cta_group::1.sync.aligned.shared::cta.b32 [%0], %1;" \
                 :: "r"(dst), "r"(n) : "memory")
#define TC_RELINQ() \
    asm volatile("tcgen05.relinquish_alloc_permit.cta_group::1.sync.aligned;")
#define TC_DEALLOC(base, n) \
    asm volatile("tcgen05.dealloc.cta_group::1.sync.aligned.b32 %0, %1;" :: "r"(base), "r"(n))
#define TC_WAIT_ST() asm volatile("tcgen05.wait::st.sync.aligned;" ::: "memory")
#define TC_WAIT_LD() asm volatile("tcgen05.wait::ld.sync.aligned;" ::: "memory")
#define TC_FENCE_BEFORE() asm volatile("tcgen05.fence::before_thread_sync;" ::: "memory")
#define TC_FENCE_AFTER()  asm volatile("tcgen05.fence::after_thread_sync;" ::: "memory")
#define TC_COMMIT(mbar) \
    asm volatile("tcgen05.commit.cta_group::1.mbarrier::arrive::one.shared::cluster.b64 [%0];" \
                 :: "r"(mbar) : "memory")
#define MBAR_INIT(a, c) \
    asm volatile("mbarrier.init.shared.b64 [%0], %1;" :: "r"(a), "r"(c) : "memory")
#define MBAR_INVAL(a) \
    asm volatile("mbarrier.inval.shared.b64 [%0];" :: "r"(a) : "memory")

#define MBAR_WAIT(mbar, par) do {                                              \
    uint32_t _m = (mbar), _p = (par), _d;                                      \
    asm volatile("{ .reg .pred p; mbarrier.try_wait.parity.acquire.cta.shared::cta.b64 p, [%1], %2; selp.b32 %0, 1, 0, p; }" \
        : "=r"(_d) : "r"(_m), "r"(_p) : "memory");                             \
    if (!_d) {                                                                 \
        asm volatile("{ .reg .pred P1; WL_%=: mbarrier.try_wait.parity.acquire.cta.shared::cta.b64 P1, [%0], %1, 0x989680; @P1 bra.uni WD_%=; bra.uni WL_%=; WD_%=: }" \
            :: "r"(_m), "r"(_p) : "memory");                                   \
    }                                                                          \
} while (0)

#define TC_ST_X32(addr, r)                                                     \
    asm volatile("tcgen05.st.sync.aligned.32x32b.x32.b32 [%0], "               \
        "{%1,%2,%3,%4,%5,%6,%7,%8,%9,%10,%11,%12,%13,%14,%15,%16,"            \
        "%17,%18,%19,%20,%21,%22,%23,%24,%25,%26,%27,%28,%29,%30,%31,%32};"    \
        :: "r"(addr),                                                          \
        "r"((r)[0]),"r"((r)[1]),"r"((r)[2]),"r"((r)[3]),"r"((r)[4]),"r"((r)[5]),"r"((r)[6]),"r"((r)[7]), \
        "r"((r)[8]),"r"((r)[9]),"r"((r)[10]),"r"((r)[11]),"r"((r)[12]),"r"((r)[13]),"r"((r)[14]),"r"((r)[15]), \
        "r"((r)[16]),"r"((r)[17]),"r"((r)[18]),"r"((r)[19]),"r"((r)[20]),"r"((r)[21]),"r"((r)[22]),"r"((r)[23]), \
        "r"((r)[24]),"r"((r)[25]),"r"((r)[26]),"r"((r)[27]),"r"((r)[28]),"r"((r)[29]),"r"((r)[30]),"r"((r)[31]) \
        : "memory")

#define TC_LD_X32(r, addr)                                                     \
    asm volatile("tcgen05.ld.sync.aligned.32x32b.x32.b32 "                     \
        "{%0,%1,%2,%3,%4,%5,%6,%7,%8,%9,%10,%11,%12,%13,%14,%15,"             \
        "%16,%17,%18,%19,%20,%21,%22,%23,%24,%25,%26,%27,%28,%29,%30,%31}, [%32];" \
        : "=r"((r)[0]),"=r"((r)[1]),"=r"((r)[2]),"=r"((r)[3]),"=r"((r)[4]),"=r"((r)[5]),"=r"((r)[6]),"=r"((r)[7]), \
          "=r"((r)[8]),"=r"((r)[9]),"=r"((r)[10]),"=r"((r)[11]),"=r"((r)[12]),"=r"((r)[13]),"=r"((r)[14]),"=r"((r)[15]), \
          "=r"((r)[16]),"=r"((r)[17]),"=r"((r)[18]),"=r"((r)[19]),"=r"((r)[20]),"=r"((r)[21]),"=r"((r)[22]),"=r"((r)[23]), \
          "=r"((r)[24]),"=r"((r)[25]),"=r"((r)[26]),"=r"((r)[27]),"=r"((r)[28]),"=r"((r)[29]),"=r"((r)[30]),"=r"((r)[31]) \
        : "r"(addr))

#define TC_MMA_F16(d, a, bd, id, en) do {                                      \
    uint32_t _e = (en);                                                        \
    asm volatile("{ .reg .pred p; setp.ne.u32 p, %4, 0;"                       \
        " tcgen05.mma.cta_group::1.kind::f16 [%0], [%1], %2, %3, {%5,%5,%5,%5}, p; }" \
        :: "r"(d), "r"(a), "l"(bd), "r"(id), "r"(_e), "r"(0u) : "memory");     \
} while (0)

__device__ __forceinline__ uint64_t make_desc(uint32_t a) {
    const uint64_t base = (2ull << 61) | (1ull << 46) | (64ull << 32) | (1ull << 16);
    return base | ((uint64_t)(a >> 4) & 0x3FFF);
}
#define IDESC 0x8200010u
#endif  // HAS_TCGEN05

// ---------------- prep: LayerNorm ----------------
__global__ __launch_bounds__(256) void k_ln(const float* __restrict__ node,
                                            const float* __restrict__ lw,
                                            const float* __restrict__ lb) {
    int j = blockIdx.x, t = threadIdx.x;
    __shared__ float red[8];
    float v = node[j * DD + t];
    float x = v;
    #pragma unroll
    for (int o = 16; o > 0; o >>= 1) x += __shfl_xor_sync(0xffffffffu, x, o);
    if ((t & 31) == 0) red[t >> 5] = x;
    __syncthreads();
    float mu = 0.f;
    #pragma unroll
    for (int w = 0; w < 8; w++) mu += red[w];
    mu *= (1.0f / 256.0f);
    __syncthreads();
    float d = v - mu;
    x = d * d;
    #pragma unroll
    for (int o = 16; o > 0; o >>= 1) x += __shfl_xor_sync(0xffffffffu, x, o);
    if ((t & 31) == 0) red[t >> 5] = x;
    __syncthreads();
    float var = 0.f;
    #pragma unroll
    for (int w = 0; w < 8; w++) var += red[w];
    var *= (1.0f / 256.0f);
    float rs = rsqrtf(var + 1e-5f);
    g_s[j * DD + t] = d * rs * lw[t] + lb[t];
}

// ---------------- prep: weight images ----------------
__global__ __launch_bounds__(256) void k_wp(const float* __restrict__ ow) {
    int bx = blockIdx.x, t = threadIdx.x;
    if (bx < 128) {
        int idx = bx * 256 + t;
        int e = idx >> 8, h = idx & 255;
        __half v = __float2half(ow[e * (2 * HH) + h]);
        uint32_t off = (uint32_t)(((h >> 6) * 16 + (e >> 3)) * 1024 + (e & 7) * 128 + (h & 63) * 2);
        off ^= (off >> 3) & 0x70;
        g_wpB[off >> 1] = v;
        g_wpT[h * EE + e] = v;
    } else {
        int idx = (bx - 128) * 256 + t;
        int h = idx >> 7, e = idx & 127;
        g_wdT[h * EE + e] = ow[e * (2 * HH) + HH + h];
    }
}

// ---------------- prep: proj GEMM ----------------
__global__ __launch_bounds__(256) void k_proj(const float* __restrict__ pw,
                                              const float* __restrict__ pb) {
    __shared__ float sA[64][33];
    __shared__ float sB[32][33];
    int t = threadIdx.x;
    int j0 = blockIdx.x * 64, h0 = blockIdx.y * 32;
    int ty = t >> 4, tx = t & 15;
    float acc[4][2] = {};
    for (int kc = 0; kc < DD; kc += 32) {
        __syncthreads();
        #pragma unroll
        for (int u = 0; u < 2; u++) {
            int idx = u * 256 + t;
            int r = idx >> 3, c4 = (idx & 7) * 4;
            float4 v = *(const float4*)(g_s + (size_t)(j0 + r) * DD + kc + c4);
            sA[r][c4 + 0] = v.x; sA[r][c4 + 1] = v.y; sA[r][c4 + 2] = v.z; sA[r][c4 + 3] = v.w;
        }
        {
            int r = t >> 3, c4 = (t & 7) * 4;
            if (r < 32) {
                float4 v = *(const float4*)(pw + (size_t)(h0 + r) * DD + kc + c4);
                sB[r][c4 + 0] = v.x; sB[r][c4 + 1] = v.y; sB[r][c4 + 2] = v.z; sB[r][c4 + 3] = v.w;
            }
        }
        __syncthreads();
        #pragma unroll
        for (int k = 0; k < 32; k++) {
            float b0 = sB[tx * 2 + 0][k];
            float b1 = sB[tx * 2 + 1][k];
            #pragma unroll
            for (int m = 0; m < 4; m++) {
                float a = sA[ty * 4 + m][k];
                acc[m][0] += a * b0;
                acc[m][1] += a * b1;
            }
        }
    }
    #pragma unroll
    for (int m = 0; m < 4; m++) {
        int j = j0 + ty * 4 + m;
        #pragma unroll
        for (int n = 0; n < 2; n++) {
            int h = h0 + tx * 2 + n;
            __half hv = __float2half(acc[m][n] + pb[h]);
            if (h < HH) g_qh[(size_t)j * HH + h] = hv;
            else        g_kh[(size_t)j * HH + (h - HH)] = hv;
        }
    }
}

// ---------------- prep: Aq / Bk' v4 — batched MLP=16, h-split 2 ----------------
__global__ __launch_bounds__(256) void k_aqbk4(const float* __restrict__ ob) {
    __shared__ float sx[256][4];        // [h][row]
    __shared__ float sp[2][4][128];     // [h-half][row][e]
    int t = threadIdx.x;
    int e = t & 127, hh = t >> 7;
    int r0 = blockIdx.x * 4;
    #pragma unroll
    for (int u = 0; u < 4; u++) {
        int idx = u * 256 + t;          // 0..1023 = 4 rows x 256 h
        int rr = idx >> 8, c = idx & 255;
        int gr = r0 + rr;
        const __half* src = (gr < NN) ? (g_qh + (size_t)gr * HH)
                                      : (g_kh + (size_t)(gr - NN) * HH);
        sx[c][rr] = __half2float(src[c]);
    }
    __syncthreads();
    float acc[4] = {};
    int hbase = hh * 128;
    #pragma unroll 2
    for (int hb = 0; hb < 128; hb += 16) {
        float wv[16];
        #pragma unroll
        for (int u = 0; u < 16; u++)
            wv[u] = g_wdT[(size_t)(hbase + hb + u) * EE + e];   // coalesced, MLP=16
        #pragma unroll
        for (int u = 0; u < 16; u++) {
            float4 x4 = *(const float4*)&sx[hbase + hb + u][0]; // broadcast
            acc[0] += x4.x * wv[u];
            acc[1] += x4.y * wv[u];
            acc[2] += x4.z * wv[u];
            acc[3] += x4.w * wv[u];
        }
    }
    #pragma unroll
    for (int rr = 0; rr < 4; rr++) sp[hh][rr][e] = acc[rr];
    __syncthreads();
    #pragma unroll
    for (int s = 0; s < 2; s++) {
        int rr = hh * 2 + s;
        float v = sp[0][rr][e] + sp[1][rr][e];
        int gr = r0 + rr;
        if (gr < NN) g_aq[(size_t)gr * EE + e] = v;
        else         g_bkp[(size_t)(gr - NN) * EE + e] = ob[e] - v;
    }
}

// ---------------- main kernel ----------------
// SMEM: misc @0 (tmem ptr, mbars @8/16); B @1024 (64K);
// sD @66560 (q staging stride 528, then 129-word transpose rows);
// AQ @134144 (stride 528, one-time); k @201728 (8K); bk @209920 (8K). total 218112
#define SB_OFF   1024
#define SD_OFF   66560
#define AQ_OFF   134144
#define SK_OFF   201728
#define SBK_OFF  209920
#define SMEM_TC  218112

#define FB_LDQ 272
#define FB_LDW 144
#define FB_SM_Q 0
#define FB_SM_B (128 * FB_LDQ * 2)
#define FB_SM_A (FB_SM_B + 256 * FB_LDW * 2)
#define FB_SM_K (FB_SM_A + 128 * FB_LDQ * 2)
#define FB_SM_BK (FB_SM_K + 512)
#define SMEM_FB (FB_SM_BK + 16 * 128 * 4)  // 221696

#define SMEM_LAUNCH ((SMEM_TC) > (SMEM_FB) ? (SMEM_TC) : (SMEM_FB))

__global__ __launch_bounds__(256, 1) void k_main(float* __restrict__ out) {
#if HAS_TCGEN05
    extern __shared__ char smem[];
    uint32_t sbase = smem_u32(smem);
    int t = threadIdx.x;
    int w = t >> 5;
    int r = t & 127;          // TMEM lane = j-row in tile
    int ch = t >> 7;          // 64-col half
    int j0 = blockIdx.x * TJ;
    int ibase = blockIdx.y * TI;

    uint32_t mb0 = sbase + 8, mb1 = sbase + 16;

    if (w == 0) { TC_ALLOC(sbase, 512); TC_RELINQ(); }
    if (t == 0) { MBAR_INIT(mb0, 1); MBAR_INIT(mb1, 1); }
    __syncthreads();
    uint32_t tmem;
    asm volatile("ld.shared.b32 %0, [%1];" : "=r"(tmem) : "r"(sbase));

    // ---- prologue: coalesced staging ----
    #pragma unroll
    for (int u = 0; u < 16; u++) {            // q (stride 528)
        int idx = u * 256 + t;
        int rr = idx >> 5, c = idx & 31;
        *(int4*)(smem + SD_OFF + rr * 528 + c * 16) =
            *(const int4*)(g_qh + (size_t)(j0 + rr) * HH + c * 8);
    }
    #pragma unroll
    for (int u = 0; u < 16; u++) {            // aq (stride 528)
        int idx = u * 256 + t;
        int rr = idx >> 5, c = idx & 31;
        *(int4*)(smem + AQ_OFF + rr * 528 + c * 16) =
            *(const int4*)(g_aq + (size_t)(j0 + rr) * EE + c * 4);
    }
    #pragma unroll
    for (int u = 0; u < 16; u++) {            // B image
        int idx = u * 256 + t;
        *(int4*)(smem + SB_OFF + idx * 16) = *(const int4*)((const char*)g_wpB + idx * 16);
    }
    #pragma unroll
    for (int u = 0; u < 2; u++) {             // k rows
        int idx = u * 256 + t;
        int rr = idx >> 5, c = idx & 31;
        *(int4*)(smem + SK_OFF + idx * 16) = *(const int4*)(g_kh + (size_t)(ibase + rr) * HH + c * 8);
    }
    #pragma unroll
    for (int u = 0; u < 2; u++) {             // bk rows
        int idx = u * 256 + t;
        int rr = idx >> 5, c = idx & 31;
        *(int4*)(smem + SBK_OFF + idx * 16) = *(const int4*)(g_bkp + (size_t)(ibase + rr) * EE + c * 4);
    }
    __syncthreads();
    // register caches: q half-row (fp16), aq half-row (fp32)
    int4 qv[16];
    float4 aqv[16];
    #pragma unroll
    for (int cc = 0; cc < 16; cc++)
        qv[cc] = *(const int4*)(smem + SD_OFF + r * 528 + ch * 256 + cc * 16);
    #pragma unroll
    for (int cc = 0; cc < 16; cc++)
        aqv[cc] = *(const float4*)(smem + AQ_OFF + r * 528 + ch * 256 + cc * 16);
    __syncthreads();

    uint32_t warp_off = (uint32_t)((r >> 5) << 21);
    uint64_t bbase = make_desc(sbase + SB_OFF);

    for (int i = 0; i <= TI; i++) {
        if (i < TI) {
            int b = i & 1;
            // ---- A'(i) = q .* k_i -> TMEM A[b] ----
            const char* kbase = smem + SK_OFF + i * 512 + ch * 256;
            uint32_t a_st = tmem + 256 + b * 128 + ch * 64 + warp_off;
            #pragma unroll
            for (int g = 0; g < 2; g++) {
                uint32_t regs[32];
                #pragma unroll
                for (int u = 0; u < 8; u++) {
                    int4 q4 = qv[g * 8 + u];
                    int4 k4 = *(const int4*)(kbase + g * 128 + u * 16);
                    const __half2* qh2 = (const __half2*)&q4;
                    const __half2* kh2 = (const __half2*)&k4;
                    #pragma unroll
                    for (int v2 = 0; v2 < 4; v2++) {
                        __half2 m = __hmul2(qh2[v2], kh2[v2]);
                        regs[u * 4 + v2] = *(const uint32_t*)&m;
                    }
                }
                TC_ST_X32(a_st + g * 32, regs);
            }
            // ---- D-init(i) = aq + bk_i -> TMEM D[b] ----
            uint32_t d_st = tmem + b * 128 + ch * 64 + warp_off;
            #pragma unroll
            for (int g = 0; g < 2; g++) {
                uint32_t di[32];
                #pragma unroll
                for (int u = 0; u < 8; u++) {
                    float4 a4 = aqv[g * 8 + u];
                    float4 b4 = *(const float4*)(smem + SBK_OFF + i * 512 + ch * 256 + (g * 8 + u) * 16);
                    di[u * 4 + 0] = __float_as_uint(a4.x + b4.x);
                    di[u * 4 + 1] = __float_as_uint(a4.y + b4.y);
                    di[u * 4 + 2] = __float_as_uint(a4.z + b4.z);
                    di[u * 4 + 3] = __float_as_uint(a4.w + b4.w);
                }
                TC_ST_X32(d_st + g * 32, di);
            }
            TC_WAIT_ST();
            TC_FENCE_BEFORE();
            __syncthreads();
            // ---- issue MMA(i), accumulate onto D-init ----
            if (w == 0) {
                TC_FENCE_AFTER();
                if (elect_one()) {
                    uint32_t d_tm = tmem + b * 128;
                    uint32_t a_tm = tmem + 256 + b * 128;
                    #pragma unroll
                    for (int s = 0; s < 16; s++) {
                        uint64_t bd = bbase + (uint64_t)((s >> 2) * 1024 + (s & 3) * 2);
                        TC_MMA_F16(d_tm, a_tm + s * 8, bd, IDESC, 1u);
                    }
                    TC_COMMIT(b ? mb1 : mb0);
                }
            }
        }
        if (i >= 1) {
            // ---- epilogue(i-1): LDTM -> 129-stride SMEM transpose -> coalesced STG ----
            int ii = i - 1;
            int pb2 = ii & 1;
            MBAR_WAIT(pb2 ? mb1 : mb0, (ii >> 1) & 1);
            TC_FENCE_AFTER();
            uint32_t d_tm = tmem + pb2 * 128 + ch * 64 + warp_off;
            // writer: word = 129*r + e  -> bank = (r+e)&31, conflict-free scalar STS
            #pragma unroll
            for (int g = 0; g < 2; g++) {
                uint32_t dr[32];
                TC_LD_X32(dr, d_tm + g * 32);
                TC_WAIT_LD();
                #pragma unroll
                for (int c = 0; c < 32; c++) {
                    int e = ch * 64 + g * 32 + c;
                    *(uint32_t*)(smem + SD_OFF + (uint32_t)(129 * r + e) * 4) = dr[c];
                }
            }
            __syncthreads();
            // reader: lanes -> e, conflict-free scalar LDS + coalesced STG.32
            int l = t & 31;
            float* obase = out + ((size_t)(ibase + ii) * NN + j0) * EE;
            #pragma unroll
            for (int jr = 0; jr < 16; jr++) {
                int j = w * 16 + jr;
                float* orow = obase + (size_t)j * EE;
                #pragma unroll
                for (int g = 0; g < 4; g++) {
                    float v = *(const float*)(smem + SD_OFF + (uint32_t)(129 * j + g * 32 + l) * 4);
                    orow[g * 32 + l] = v;
                }
            }
            __syncthreads();
        }
    }

    __syncthreads();
    if (t == 0) { MBAR_INVAL(mb0); MBAR_INVAL(mb1); }
    __syncthreads();
    if (w == 0) { TC_DEALLOC(tmem, 512); }
#else
    // -------- wmma fallback (family-generic pass) --------
    using namespace nvcuda;
    extern __shared__ char smem_raw[];
    __half* sQ  = (__half*)(smem_raw + FB_SM_Q);
    __half* sB  = (__half*)(smem_raw + FB_SM_B);
    __half* sA  = (__half*)(smem_raw + FB_SM_A);
    __half* sK  = (__half*)(smem_raw + FB_SM_K);
    float*  sBk = (float*)(smem_raw + FB_SM_BK);

    int t = threadIdx.x;
    int w = t >> 5;
    int wj = w >> 1;
    int we = w & 1;
    int j0 = blockIdx.x * TJ;
    int ibase = blockIdx.y * TI;

    for (int idx = t; idx < 4096; idx += 256) {
        int r = idx >> 5, c = idx & 31;
        *(int4*)(sQ + r * FB_LDQ + c * 8) = *(const int4*)(g_qh + (size_t)(j0 + r) * HH + c * 8);
    }
    for (int idx = t; idx < 4096; idx += 256) {
        int r = idx >> 4, c = idx & 15;
        *(int4*)(sB + r * FB_LDW + c * 8) = *(const int4*)(g_wpT + (size_t)r * EE + c * 8);
    }

    for (int it = 0; it < TI; it++) {
        int i = ibase + it;
        if (t < 32) *(int4*)(sK + t * 8) = *(const int4*)(g_kh + (size_t)i * HH + t * 8);
        {
            const float4* src = (const float4*)(g_bkp + (size_t)i * EE);
            #pragma unroll
            for (int idx = t; idx < 512; idx += 256) {
                int c = idx & 31;
                ((float4*)sBk)[idx] = src[c];
            }
        }
        __syncthreads();

        for (int idx = t; idx < 4096; idx += 256) {
            int r = idx >> 5, c = idx & 31;
            int4 qv = *(const int4*)(sQ + r * FB_LDQ + c * 8);
            int4 kv = *(const int4*)(sK + c * 8);
            const __half2* qh2 = (const __half2*)&qv;
            const __half2* kh2 = (const __half2*)&kv;
            int4 av;
            __half2* ah = (__half2*)&av;
            ah[0] = __hmul2(qh2[0], kh2[0]);
            ah[1] = __hmul2(qh2[1], kh2[1]);
            ah[2] = __hmul2(qh2[2], kh2[2]);
            ah[3] = __hmul2(qh2[3], kh2[3]);
            *(int4*)(sA + r * FB_LDQ + c * 8) = av;
        }
        __syncthreads();

        wmma::fragment<wmma::accumulator, 16, 16, 16, float> acc[2][4];
        #pragma unroll
        for (int m = 0; m < 2; m++)
            #pragma unroll
            for (int n = 0; n < 4; n++)
                wmma::fill_fragment(acc[m][n], 0.0f);

        #pragma unroll
        for (int kk = 0; kk < HH; kk += 16) {
            wmma::fragment<wmma::matrix_a, 16, 16, 16, __half, wmma::row_major> af[2];
            wmma::fragment<wmma::matrix_b, 16, 16, 16, __half, wmma::row_major> bf[4];
            #pragma unroll
            for (int m = 0; m < 2; m++)
                wmma::load_matrix_sync(af[m], sA + (wj * 32 + m * 16) * FB_LDQ + kk, FB_LDQ);
            #pragma unroll
            for (int n = 0; n < 4; n++)
                wmma::load_matrix_sync(bf[n], sB + kk * FB_LDW + we * 64 + n * 16, FB_LDW);
            #pragma unroll
            for (int m = 0; m < 2; m++)
                #pragma unroll
                for (int n = 0; n < 4; n++)
                    wmma::mma_sync(acc[m][n], af[m], bf[n], acc[m][n]);
        }

        #pragma unroll
        for (int m = 0; m < 2; m++) {
            int jr = j0 + wj * 32 + m * 16;
            #pragma unroll
            for (int n = 0; n < 4; n++) {
                int ec = we * 64 + n * 16;
                wmma::fragment<wmma::accumulator, 16, 16, 16, float> aqf, bkf;
                wmma::load_matrix_sync(aqf, g_aq + (size_t)jr * EE + ec, EE, wmma::mem_row_major);
                wmma::load_matrix_sync(bkf, sBk + ec, 128, wmma::mem_row_major);
                #pragma unroll
                for (int u = 0; u < acc[m][n].num_elements; u++)
                    acc[m][n].x[u] += aqf.x[u] + bkf.x[u];
                wmma::store_matrix_sync(out + ((size_t)i * NN + jr) * EE + ec,
                                        acc[m][n], EE, wmma::mem_row_major);
            }
        }
        __syncthreads();
    }
#endif
}

// ---------------- launcher ----------------
extern "C" void kernel_launch(void* const* d_in, const int* in_sizes, int n_in,
                              void* d_out, int out_size) {
    const float* node = (const float*)d_in[0];
    const float* ln_w = (const float*)d_in[1];
    const float* ln_b = (const float*)d_in[2];
    const float* pw   = (const float*)d_in[3];
    const float* pb   = (const float*)d_in[4];
    const float* ow   = (const float*)d_in[5];
    const float* ob   = (const float*)d_in[6];
    float* out = (float*)d_out;

    cudaFuncSetAttribute(k_main, cudaFuncAttributeMaxDynamicSharedMemorySize, SMEM_LAUNCH);

    k_ln<<<NN, 256>>>(node, ln_w, ln_b);
    k_wp<<<256, 256>>>(ow);
    {
        dim3 g(NN / 64, (2 * HH) / 32);
        k_proj<<<g, 256>>>(pw, pb);
    }
    k_aqbk4<<<2 * NN / 4, 256>>>(ob);
    {
        dim3 g(NN / TJ, NN / TI);
        k_main<<<g, 256, SMEM_LAUNCH>>>(out);
    }
}